// round 17
// baseline (speedup 1.0000x reference)
#include <cuda_runtime.h>

// Problem constants
#define PP 12
#define BB 4
#define KSTEP 12
#define TE_DEPTH 168
#define NUM_CELLS 1024   // 32*32
#define PQ 24            // P + Q

// Output layout (tuple flattened, row-major each):
#define OFF_Y    0
#define OFF_X    4096
#define OFF_T    53248
#define OFF_R    446464
#define OFF_RES  495616

// Dynamic smem layout (floats), contiguous zero block first:
//  tp    @ 0      : 8 planes 34x34, stride 34 (9248)
//  xs    @ 9248   : 2 buffers 38 rows x 40 stride, 2-ring pad (2*1520 = 3040)
//  rstp  @ 12288  : restart plane 34x34 (1156)
//  biasp @ 13444  : bias plane 34x34 (1156)          [zero block = 14600 floats]
//  stage @ 14600  : 352*13 this-third results staging (4576)
//  wte_s @ 19176  : Wt[0:168] rows (1344)
//  wr_s  @ 20520  : Wr[0:168] (168)
//  wb_s  @ 20688  : Wb[0:168] (168)
#define TP_OFF    0
#define XS_OFF    9248
#define XS_STRIDE 40
#define XS_SIZE   (38 * XS_STRIDE)     // 1520
#define RST_OFF   12288
#define BIA_OFF   13444
#define STG_OFF   14600
#define WTE_OFF   19176
#define WR_OFF    20520
#define WB_OFF    20688
#define SMEM_FLOATS 20856   // 83424 B
#define ZERO_FLOATS 14600   // 3650 float4

// Three CTAs per (b,p) plane (grid=144 ≈ 1 CTA/SM): all compute the full
// plane, each stores only its third. Loop uses operator squaring: 6 smem
// round-trips produce 12 steps (x_{k+1} via 3x3 L, x_{k+2} via 5x5 L^2).

__global__ __launch_bounds__(1024, 1) void rwr_kernel(
    const float* __restrict__ X,
    const int*   __restrict__ TE,
    const float* __restrict__ Wt,   // (1192, 8)
    const float* __restrict__ Wr,   // (1192, 1)
    const float* __restrict__ Wb,   // (1192, 1)
    float*       __restrict__ out)
{
    extern __shared__ __align__(16) float sm[];
    float* tp    = sm + TP_OFF;
    float* xs    = sm + XS_OFF;
    float* rstp  = sm + RST_OFF;
    float* biasp = sm + BIA_OFF;
    float* stage = sm + STG_OFF;
    float* wte_s = sm + WTE_OFF;
    float* wr_s  = sm + WR_OFF;
    float* wb_s  = sm + WB_OFF;

    const int bp   = blockIdx.x / 3;    // 0..47
    const int part = blockIdx.x % 3;
    const int b    = bp / PP;
    const int p    = bp % PP;
    const int cell = threadIdx.x;       // 0..1023
    const int h    = cell >> 5;
    const int w    = cell & 31;

    const int base  = part * 352;                     // 0 / 352 / 704
    const int ncell = (part == 2) ? 320 : 352;
    const bool mine = (cell >= base) && (cell < base + ncell);   // warp-uniform

    // ---- issue ALL independent global loads at cycle 0 (max MLP, 32 warps) ----
    const float x0 = X[bp * NUM_CELLS + cell];
    const int te_day  = TE[(b * PQ + p) * 2 + 0];
    const int te_hour = TE[(b * PQ + p) * 2 + 1];
    const int cr = TE_DEPTH + cell;

    const float4* wc4 = reinterpret_cast<const float4*>(Wt + (size_t)cr * 8);
    const float4 wc_lo = wc4[0];
    const float4 wc_hi = wc4[1];
    const float wr_c = Wr[cr];
    const float wb_c = Wb[cr];

    // speculative te-block load -> smem
    if (cell < 420) {
        float4 v;
        if (cell < 336)      v = reinterpret_cast<const float4*>(Wt)[cell];
        else if (cell < 378) v = reinterpret_cast<const float4*>(Wr)[cell - 336];
        else                 v = reinterpret_cast<const float4*>(Wb)[cell - 378];
        float4* dst;
        if (cell < 336)      dst = reinterpret_cast<float4*>(wte_s) + cell;
        else if (cell < 378) dst = reinterpret_cast<float4*>(wr_s) + (cell - 336);
        else                 dst = reinterpret_cast<float4*>(wb_s) + (cell - 378);
        *dst = v;
    }

    // ---- float4 zero of tp + xs + rstp + biasp (3650 float4) ----
    {
        float4* z4 = reinterpret_cast<float4*>(sm);
        const float4 zv = make_float4(0.f, 0.f, 0.f, 0.f);
        z4[cell] = zv;
        z4[cell + 1024] = zv;
        z4[cell + 2048] = zv;
        if (cell < 578) z4[cell + 3072] = zv;
    }

    __syncthreads();   // BAR#1: te-block resident + zero done

    // ---- read te row from smem ----
    const int te = te_day * 24 + te_hour;            // < 168
    const float4 wt_lo = reinterpret_cast<const float4*>(wte_s)[te * 2];
    const float4 wt_hi = reinterpret_cast<const float4*>(wte_s)[te * 2 + 1];
    const float wr_te = wr_s[te];
    const float wb_te = wb_s[te];

    // ---- softmax over 8 dirs ----
    float e[8], s = 0.f;
    e[0] = __expf(wt_lo.x + wc_lo.x);  e[1] = __expf(wt_lo.y + wc_lo.y);
    e[2] = __expf(wt_lo.z + wc_lo.z);  e[3] = __expf(wt_lo.w + wc_lo.w);
    e[4] = __expf(wt_hi.x + wc_hi.x);  e[5] = __expf(wt_hi.y + wc_hi.y);
    e[6] = __expf(wt_hi.z + wc_hi.z);  e[7] = __expf(wt_hi.w + wc_hi.w);
    #pragma unroll
    for (int d = 0; d < 8; d++) s += e[d];
    const float inv_s = __fdividef(1.0f, s);
    float tpv[8];
    #pragma unroll
    for (int d = 0; d < 8; d++) tpv[d] = e[d] * inv_s;

    const float rz = wr_te + wr_c;
    const float rst_c = __fdividef(1.0f, 1.0f + __expf(-rz));
    const float omr_c = 1.0f - rst_c;
    const float bias0 = (wb_te + wb_c) * x0;

    // ---- static outputs: ONLY this CTA's third ----
    if (mine) {
        float4* t4 = reinterpret_cast<float4*>(out + OFF_T + (size_t)(bp * NUM_CELLS + cell) * 8);
        t4[0] = make_float4(tpv[0], tpv[1], tpv[2], tpv[3]);
        t4[1] = make_float4(tpv[4], tpv[5], tpv[6], tpv[7]);
        out[OFF_R + bp * NUM_CELLS + cell] = rst_c;
        stage[(cell - base) * 13] = x0;
    }

    // ---- fill planes: tp interior, restart, bias, x0 into xs buf0 ----
    const int tctr = (h + 1) * 34 + (w + 1);
    #pragma unroll
    for (int d = 0; d < 8; d++) tp[d * 1156 + tctr] = tpv[d];
    rstp[tctr]  = rst_c;
    biasp[tctr] = bias0;
    const int ctr = (h + 2) * XS_STRIDE + (w + 2);
    xs[ctr] = x0;     // buf 0

    __syncthreads();   // BAR#2: all planes + xs buf0 + stage[0] ready

    // DIRS d: 0:(-1,-1) 1:(-1,0) 2:(-1,1) 3:(0,-1) 4:(0,1) 5:(1,-1) 6:(1,0) 7:(1,1)
    const int DR[8]    = {-1,-1,-1, 0, 0, 1, 1, 1};
    const int DC[8]    = {-1, 0, 1,-1, 1,-1, 0, 1};
    const int DOF34[8] = {-35,-34,-33,-1, 1, 33, 34, 35};
    const int IDX5[8]  = {-6, -5, -4, -1, 1,  4,  5,  6};   // DR*5+DC

    // one-step stencil coeffs: ow[d] = omr_c * tp[d](c + delta_d)
    float ow[8];
    #pragma unroll
    for (int d = 0; d < 8; d++)
        ow[d] = omr_c * tp[d * 1156 + tctr + DOF34[d]];

    // bias for double-step: b2 = rst_c*b + omr_c*sum_d win[d]*b(n_d) + b
    float b2;
    {
        float sb = 0.f;
        #pragma unroll
        for (int d = 0; d < 8; d++)
            sb = fmaf(ow[d], biasp[tctr + DOF34[d]], sb);   // ow = omr*win folds omr in
        b2 = fmaf(rst_c, bias0, sb) + bias0;
    }

    // ---- build W2 = L^2 row for this cell (25 coeffs, 5x5) ----
    float W2[25];
    #pragma unroll
    for (int i = 0; i < 25; i++) W2[i] = 0.f;
    W2[12] = rst_c * rst_c;
    #pragma unroll
    for (int d = 0; d < 8; d++)
        W2[12 + IDX5[d]] += rst_c * ow[d];

    #pragma unroll
    for (int d = 0; d < 8; d++) {
        const bool vd = ((unsigned)(h + DR[d]) < 32u) && ((unsigned)(w + DC[d]) < 32u);
        const int  mo = vd ? DOF34[d] : 0;       // clamp: coeff is 0 anyway (ow[d]=0)
        const float Lcm   = ow[d];
        const float rst_m = rstp[tctr + mo];
        const float Lo    = Lcm * (1.0f - rst_m);
        W2[12 + IDX5[d]] += Lcm * rst_m;
        #pragma unroll
        for (int e2 = 0; e2 < 8; e2++) {
            const float t = tp[e2 * 1156 + tctr + mo + DOF34[e2]];
            W2[12 + IDX5[d] + IDX5[e2]] += Lo * t;
        }
    }

    // ---- 6 rounds x 2 steps ----
    float* sp = stage + (cell - base) * 13;
    float x = x0;

    #pragma unroll
    for (int j = 0; j < 6; j++) {
        float* xb = xs + (j & 1) * XS_SIZE;
        if (j > 0) {
            xb[ctr] = x;
            __syncthreads();
        }
        // x_{k+1}: 3x3 with ow (reads the 8 ring values)
        // x_{k+2}: 5x5 with W2 over v[25]
        float acc0 = b2, acc1 = 0.f, acc2 = 0.f, acc3 = 0.f;
        float x1a = fmaf(rst_c, x, bias0);
        float x1b = 0.f;
        #pragma unroll
        for (int dy = -2; dy <= 2; dy++) {
            #pragma unroll
            for (int dx = -2; dx <= 2; dx++) {
                const int i5 = (dy + 2) * 5 + (dx + 2);
                float v;
                if (dy == 0 && dx == 0) v = x;
                else v = xb[ctr + dy * XS_STRIDE + dx];
                // 4-way accumulator rotation for x2
                const int r4 = i5 & 3;
                if      (r4 == 0) acc0 = fmaf(W2[i5], v, acc0);
                else if (r4 == 1) acc1 = fmaf(W2[i5], v, acc1);
                else if (r4 == 2) acc2 = fmaf(W2[i5], v, acc2);
                else              acc3 = fmaf(W2[i5], v, acc3);
                // x1: inner ring only
                if (dy >= -1 && dy <= 1 && dx >= -1 && dx <= 1 && !(dy == 0 && dx == 0)) {
                    // map (dy,dx) -> dir index
                    const int dd = (dy + 1) * 3 + (dx + 1);
                    const int d8 = (dd < 4) ? dd : dd - 1;   // skip center
                    if (d8 & 1) x1b = fmaf(ow[d8], v, x1b);
                    else        x1a = fmaf(ow[d8], v, x1a);
                }
            }
        }
        const float x1 = x1a + x1b;
        const float x2 = (acc0 + acc1) + (acc2 + acc3);
        if (mine) { sp[2 * j + 1] = x1; sp[2 * j + 2] = x2; }
        x = x2;
    }

    // final state x + Y: only this CTA's third
    if (mine) {
        out[OFF_X + bp * NUM_CELLS + cell] = x;
        if (p == PP - 1)
            out[OFF_Y + b * NUM_CELLS + cell] = x;
    }

    // ---- one barrier, then 1024-thread coalesced dump of this third ----
    __syncthreads();
    const int n4 = (ncell * 13) >> 2;          // 1144 or 1040
    const float4* s4 = reinterpret_cast<const float4*>(stage);
    float4* o4 = reinterpret_cast<float4*>(out + OFF_RES + (size_t)bp * (NUM_CELLS * 13))
                 + ((base * 13) >> 2);
    if (cell < n4) o4[cell] = s4[cell];
    if (cell < n4 - 1024) o4[cell + 1024] = s4[cell + 1024];
}

extern "C" void kernel_launch(void* const* d_in, const int* in_sizes, int n_in,
                              void* d_out, int out_size) {
    const float* X  = (const float*)d_in[0];
    const int*   TE = (const int*)d_in[1];
    const float* Wt = (const float*)d_in[2];
    const float* Wr = (const float*)d_in[3];
    const float* Wb = (const float*)d_in[4];
    float* out = (float*)d_out;
    const int smem_bytes = SMEM_FLOATS * 4;   // 83424 B
    cudaFuncSetAttribute(rwr_kernel, cudaFuncAttributeMaxDynamicSharedMemorySize, smem_bytes);
    rwr_kernel<<<BB * PP * 3, 1024, smem_bytes>>>(X, TE, Wt, Wr, Wb, out);
}